// round 2
// baseline (speedup 1.0000x reference)
#include <cuda_runtime.h>

// IDGNN, restructured:
//   L = 2 layers, K = 2 hops, N = 256 nodes, D = 128 features.
//   out[t] = v_t + S_t*w2[1,0] + deg_t*b2[1,0] + self_t*(g1(v_t) - g0(v_t))
//   where p_i = MLP_{0,i}(x);  q0 = A*p0;  u = x + q0;  d = p1 - p0
//         v_t = u_t + self_t*d_t
//         Un_i = u*W1e[1,i]; Dt_i = d*W1e[1,i]   (W1e = w1[:D]+w1[D:], z=cat([H,H]))
//         S_t = sum_{n in N(t)} relu(Un0[n] + Dt0[t] + b1[1,0])
//         g_i(v_t): hidden = relu(Un_i[t] + self_t*Dt_i[t] + b1[1,i]); dot w2[1,i] + b2[1,i]
// The 2-hop mask M never matters: only (t,t) and 1-hop pairs are read, both always in M.
//
// edge_index dtype hazard: reference says int64 but JAX default x64-disabled
// materializes int32. We detect at runtime (int64-as-int32 has all-zero odd
// words since node ids are in [0,256)) and mask indices with &255 so a wrong
// guess can never fault.

#define NN 256
#define DD 128

// ---- device scratch (no allocations allowed) ----
__device__ unsigned g_adj[NN * 8];     // symmetric adjacency bitmask per row
__device__ int      g_deg[NN];
__device__ int      g_self[NN];
__device__ float    g_W1e[4 * DD * DD];  // [l*2+i][k][c] = w1[l,i,k,c] + w1[l,i,k+128,c]
__device__ float    g_p0[NN * DD];
__device__ float    g_p1[NN * DD];
__device__ float    g_u[NN * DD];
__device__ float    g_d[NN * DD];
__device__ float    g_UD[4][NN * DD];  // 0:Un0  1:Dt0  2:Un1  3:Dt1

// ---------------------------------------------------------------------------
// K0: adjacency bitmasks + degree + self-loop flag + W1eff. grid=256, block=128
// ---------------------------------------------------------------------------
__global__ void k_build(const int* __restrict__ ei32, int E,
                        const float* __restrict__ w1) {
    int t = blockIdx.x, tid = threadIdx.x;
    __shared__ unsigned m[8];
    __shared__ int degS;
    if (tid < 8) m[tid] = 0u;
    if (tid == 0) degS = 0;
    __syncthreads();

    // dtype sniff: int64 edge ids (nonneg < 256) => odd int32 words all zero.
    bool is64 = true;
#pragma unroll
    for (int i = 1; i < 129; i += 2)
        if (ei32[i] != 0) { is64 = false; break; }

    for (int e = tid; e < E; e += 128) {
        int a, b;
        if (is64) { a = ei32[2 * e];  b = ei32[2 * (E + e)]; }
        else      { a = ei32[e];      b = ei32[E + e]; }
        a &= 255; b &= 255;
        if (a == t) atomicOr(&m[b >> 5], 1u << (b & 31));
        if (b == t) atomicOr(&m[a >> 5], 1u << (a & 31));
    }
    __syncthreads();
    if (tid < 8) {
        g_adj[t * 8 + tid] = m[tid];
        atomicAdd(&degS, __popc(m[tid]));
    }
    __syncthreads();
    if (tid == 0) {
        g_deg[t]  = degS;
        g_self[t] = (m[t >> 5] >> (t & 31)) & 1;
    }
    // W1eff: 65536 elems total; block t handles flat [t*256, t*256+256)
#pragma unroll
    for (int r = 0; r < 2; r++) {
        int flat = t * 256 + r * 128 + tid;   // (l*2+i)*16384 + k*128 + c
        int li   = flat >> 14;
        int rem  = flat & 16383;
        int src  = li * 32768 + rem;          // w1[((l*2+i)*256 + k)*128 + c]
        g_W1e[flat] = w1[src] + w1[src + 16384];
    }
}

// ---------------------------------------------------------------------------
// K1: p_i[r] = relu(x_r*W1e[0,i]+b1[0,i])*w2[0,i]+b2[0,i]. grid=(256,2), blk=128
// ---------------------------------------------------------------------------
__global__ void k_p(const float* __restrict__ x, const float* __restrict__ b1,
                    const float* __restrict__ w2, const float* __restrict__ b2) {
    int r = blockIdx.x, i = blockIdx.y, c = threadIdx.x;
    __shared__ float Xs[DD];
    __shared__ float Hs[DD];
    Xs[c] = x[r * DD + c];
    __syncthreads();
    const float* W = g_W1e + i * DD * DD;   // l = 0
    float a0 = 0.f, a1 = 0.f, a2 = 0.f, a3 = 0.f;
#pragma unroll 8
    for (int k = 0; k < DD; k += 4) {
        a0 = fmaf(Xs[k],     W[(k)*DD + c],     a0);
        a1 = fmaf(Xs[k + 1], W[(k + 1)*DD + c], a1);
        a2 = fmaf(Xs[k + 2], W[(k + 2)*DD + c], a2);
        a3 = fmaf(Xs[k + 3], W[(k + 3)*DD + c], a3);
    }
    Hs[c] = fmaxf((a0 + a1) + (a2 + a3) + b1[i * DD + c], 0.f);
    __syncthreads();
    const float* W2 = w2 + i * DD * DD;     // w2[0,i]
    a0 = a1 = a2 = a3 = 0.f;
#pragma unroll 8
    for (int k = 0; k < DD; k += 4) {
        a0 = fmaf(Hs[k],     W2[(k)*DD + c],     a0);
        a1 = fmaf(Hs[k + 1], W2[(k + 1)*DD + c], a1);
        a2 = fmaf(Hs[k + 2], W2[(k + 2)*DD + c], a2);
        a3 = fmaf(Hs[k + 3], W2[(k + 3)*DD + c], a3);
    }
    float p = (a0 + a1) + (a2 + a3) + b2[i * DD + c];
    if (i) g_p1[r * DD + c] = p; else g_p0[r * DD + c] = p;
}

// ---------------------------------------------------------------------------
// K2: Un0/Dt0/Un1/Dt1 = {u,d} * W1e[1,{0,1}] (u,d rebuilt per block; u,d stored)
// grid=(256,4), block=128. combo: bit0 = (d vs u), bit1 = i
// ---------------------------------------------------------------------------
__global__ void k_ud(const float* __restrict__ x) {
    int r = blockIdx.x, combo = blockIdx.y, c = threadIdx.x;
    __shared__ float Ss[DD];
    float v;
    if (combo & 1) {                        // d = p1 - p0
        v = g_p1[r * DD + c] - g_p0[r * DD + c];
        if (combo == 1) g_d[r * DD + c] = v;
    } else {                                // u = x + sum_{m in N(r)} p0[m]
        float acc = x[r * DD + c];
#pragma unroll
        for (int w = 0; w < 8; w++) {
            unsigned bits = g_adj[r * 8 + w];
            while (bits) {
                int b = __ffs(bits) - 1;
                bits &= bits - 1;
                acc += g_p0[(w * 32 + b) * DD + c];
            }
        }
        v = acc;
        if (combo == 0) g_u[r * DD + c] = v;
    }
    Ss[c] = v;
    __syncthreads();
    const float* W = g_W1e + (2 + (combo >> 1)) * DD * DD;  // W1e[1,i]
    float a0 = 0.f, a1 = 0.f, a2 = 0.f, a3 = 0.f;
#pragma unroll 8
    for (int k = 0; k < DD; k += 4) {
        a0 = fmaf(Ss[k],     W[(k)*DD + c],     a0);
        a1 = fmaf(Ss[k + 1], W[(k + 1)*DD + c], a1);
        a2 = fmaf(Ss[k + 2], W[(k + 2)*DD + c], a2);
        a3 = fmaf(Ss[k + 3], W[(k + 3)*DD + c], a3);
    }
    g_UD[combo][r * DD + c] = (a0 + a1) + (a2 + a3);
}

// ---------------------------------------------------------------------------
// K3: hidden-sum over neighbors, diag MLP hiddens, final dots, output.
// grid=256, block=128
// ---------------------------------------------------------------------------
__global__ void k_out(const float* __restrict__ b1, const float* __restrict__ w2,
                      const float* __restrict__ b2, float* __restrict__ out) {
    int t = blockIdx.x, c = threadIdx.x;
    __shared__ float Ssum[DD];
    __shared__ float H0s[DD];
    __shared__ float H1s[DD];
    float dt0 = g_UD[1][t * DD + c];
    float dt1 = g_UD[3][t * DD + c];
    float b10 = b1[2 * DD + c];             // b1[1,0]
    float b11 = b1[3 * DD + c];             // b1[1,1]
    int self  = g_self[t];
    float sf  = (float)self;

    float acc = 0.f;
#pragma unroll
    for (int w = 0; w < 8; w++) {
        unsigned bits = g_adj[t * 8 + w];
        while (bits) {
            int b = __ffs(bits) - 1;
            bits &= bits - 1;
            acc += fmaxf(g_UD[0][(w * 32 + b) * DD + c] + dt0 + b10, 0.f);
        }
    }
    Ssum[c] = acc;
    H0s[c] = fmaxf(g_UD[0][t * DD + c] + sf * dt0 + b10, 0.f);
    H1s[c] = fmaxf(g_UD[2][t * DD + c] + sf * dt1 + b11, 0.f);
    __syncthreads();

    const float* W20 = w2 + 2 * DD * DD;    // w2[1,0]
    float a0 = 0.f, a1 = 0.f, a2 = 0.f, a3 = 0.f;
#pragma unroll 8
    for (int k = 0; k < DD; k += 4) {
        a0 = fmaf(Ssum[k],     W20[(k)*DD + c],     a0);
        a1 = fmaf(Ssum[k + 1], W20[(k + 1)*DD + c], a1);
        a2 = fmaf(Ssum[k + 2], W20[(k + 2)*DD + c], a2);
        a3 = fmaf(Ssum[k + 3], W20[(k + 3)*DD + c], a3);
    }
    float res = (a0 + a1) + (a2 + a3) + (float)g_deg[t] * b2[2 * DD + c];
    // v_t = u_t + self*d_t
    res += g_u[t * DD + c] + sf * g_d[t * DD + c];

    if (self) {                             // block-uniform branch
        const float* W21 = w2 + 3 * DD * DD;
        float d0 = 0.f, d1 = 0.f;
#pragma unroll 8
        for (int k = 0; k < DD; k++) {
            d0 = fmaf(H0s[k], W20[k * DD + c], d0);
            d1 = fmaf(H1s[k], W21[k * DD + c], d1);
        }
        res += (d1 + b2[3 * DD + c]) - (d0 + b2[2 * DD + c]);
    }
    out[t * DD + c] = res;
}

extern "C" void kernel_launch(void* const* d_in, const int* in_sizes, int n_in,
                              void* d_out, int out_size) {
    const float* x  = (const float*)d_in[0];
    const float* w1 = (const float*)d_in[1];
    const float* b1 = (const float*)d_in[2];
    const float* w2 = (const float*)d_in[3];
    const float* b2 = (const float*)d_in[4];
    const int*   ei = (const int*)d_in[5];   // int32 view; dtype sniffed on device
    int E = in_sizes[5] / 2;                 // shape (2, E) either dtype
    float* out = (float*)d_out;

    k_build<<<NN, 128>>>(ei, E, w1);
    k_p    <<<dim3(NN, 2), 128>>>(x, b1, w2, b2);
    k_ud   <<<dim3(NN, 4), 128>>>(x);
    k_out  <<<NN, 128>>>(b1, w2, b2, out);
}